// round 15
// baseline (speedup 1.0000x reference)
#include <cuda_runtime.h>
#include <cuda_bf16.h>
#include <cstdint>
#include <stdint.h>
#include <math.h>

#define BATCH 2
#define NSEQ 2048
#define DIM 1024
#define NH 16
#define HD 64
#define ROWS (BATCH*NSEQ)          // 4096
#define BELEMS (NSEQ*DIM)          // 2097152

// ---------------- device scratch ----------------
__device__ double g_xpart_s[BATCH*64], g_xpart_q[BATCH*64];
__device__ double g_wpart[5*64];
__device__ double g_zpart_s[ROWS], g_zpart_q[ROWS];
__device__ float  g_zmu[BATCH], g_zrstd[BATCH];
__device__ __nv_bfloat16 g_Aq [ROWS*DIM];
__device__ __nv_bfloat16 g_A2q[ROWS*DIM];
__device__ float  g_arow [ROWS];
__device__ float  g_a2row[ROWS];
__device__ __nv_bfloat16 g_Wt[5*DIM*DIM];
__device__ __nv_bfloat16 g_Qh[BATCH*NH*NSEQ*HD], g_Ql[BATCH*NH*NSEQ*HD];
__device__ __nv_bfloat16 g_Kh[BATCH*NH*NSEQ*HD], g_Kl[BATCH*NH*NSEQ*HD];
__device__ __nv_bfloat16 g_Vh[BATCH*NH*NSEQ*HD], g_Vl[BATCH*NH*NSEQ*HD];
__device__ float  g_G [ROWS*DIM];
__device__ float  g_Y [ROWS*DIM];
__device__ float  g_Z [ROWS*DIM];

// ---------------- fused reductions ----------------
__global__ void k_reduce_all(const float* __restrict__ x,
                             const float* wa, const float* wb, const float* wc,
                             const float* wd, const float* we) {
    int y = blockIdx.y;
    __shared__ double shs[256], shq[256];
    if (y < BATCH) {
        const float* p = x + (size_t)y * BELEMS;
        double s = 0.0, q = 0.0;
        for (int i = blockIdx.x * blockDim.x + threadIdx.x; i < BELEMS;
             i += gridDim.x * blockDim.x) {
            double v = (double)p[i];
            s += v; q += v * v;
        }
        shs[threadIdx.x] = s; shq[threadIdx.x] = q; __syncthreads();
        for (int o = 128; o > 0; o >>= 1) {
            if (threadIdx.x < o) {
                shs[threadIdx.x] += shs[threadIdx.x + o];
                shq[threadIdx.x] += shq[threadIdx.x + o];
            }
            __syncthreads();
        }
        if (threadIdx.x == 0) {
            g_xpart_s[y * 64 + blockIdx.x] = shs[0];
            g_xpart_q[y * 64 + blockIdx.x] = shq[0];
        }
    } else {
        const float* ws[5] = {wa, wb, wc, wd, we};
        const float* w = ws[y - 2];
        double s = 0.0;
        for (int i = blockIdx.x * blockDim.x + threadIdx.x; i < DIM * DIM;
             i += gridDim.x * blockDim.x)
            s += (double)fabsf(w[i]);
        shs[threadIdx.x] = s; __syncthreads();
        for (int o = 128; o > 0; o >>= 1) {
            if (threadIdx.x < o) shs[threadIdx.x] += shs[threadIdx.x + o];
            __syncthreads();
        }
        if (threadIdx.x == 0) g_wpart[(y - 2) * 64 + blockIdx.x] = shs[0];
    }
}

// inline finalize helpers (bit-identical to old k_fin1 chain)
__device__ __forceinline__ float fin_wsc(int wi) {
    double s = 0.0;
    for (int i = 0; i < 64; i++) s += g_wpart[wi * 64 + i];
    float m = (float)(s / (double)(DIM * DIM));
    if (m < 1e-5f) m = 1e-5f;
    return 1.0f / m;            // quant scale
}
__device__ __forceinline__ void fin_x(int b, float& mu, float& rs) {
    double s = 0.0, q = 0.0;
    for (int i = 0; i < 64; i++) { s += g_xpart_s[b*64+i]; q += g_xpart_q[b*64+i]; }
    double n = (double)BELEMS;
    double mud = s / n;
    double var = q / n - mud * mud;
    mu = (float)mud;
    rs = (float)(1.0 / sqrt(var + 1e-5));
}

// ---------------- fused prep: y<5 ternarize weight y, y==5 quantize x acts ----------------
__global__ void k_prep(const float* __restrict__ x,
                       const float* wa, const float* wb, const float* wc,
                       const float* wd, const float* we) {
    int y = blockIdx.y;
    __shared__ float sh[256];
    __shared__ float sp[2];
    if (y < 5) {
        if (threadIdx.x == 0) sp[0] = fin_wsc(y);
        __syncthreads();
        float sc = sp[0];
        const float* ws[5] = {wa, wb, wc, wd, we};
        const float* w = ws[y];
        __nv_bfloat16* out = g_Wt + (size_t)y * DIM * DIM;
        for (int i = blockIdx.x * blockDim.x + threadIdx.x; i < DIM * DIM / 4;
             i += gridDim.x * blockDim.x) {
            float4 v = *(const float4*)(w + i * 4);
            float t0 = fminf(fmaxf(rintf(v.x * sc), -1.0f), 1.0f);
            float t1 = fminf(fmaxf(rintf(v.y * sc), -1.0f), 1.0f);
            float t2 = fminf(fmaxf(rintf(v.z * sc), -1.0f), 1.0f);
            float t3 = fminf(fmaxf(rintf(v.w * sc), -1.0f), 1.0f);
            __nv_bfloat162* o2 = (__nv_bfloat162*)(out + i * 4);
            o2[0] = __floats2bfloat162_rn(t0, t1);
            o2[1] = __floats2bfloat162_rn(t2, t3);
        }
        return;
    }
    int row = blockIdx.x;
    int b = row >> 11;
    if (threadIdx.x == 0) fin_x(b, sp[0], sp[1]);
    __syncthreads();
    float mu = sp[0], rs = sp[1];
    const float* p = x + (size_t)row * DIM;
    __nv_bfloat16* op = g_Aq + (size_t)row * DIM;

    int c0 = threadIdx.x * 4;
    float4 vv = *(const float4*)(p + c0);
    float v0 = (vv.x - mu) * rs, v1 = (vv.y - mu) * rs;
    float v2 = (vv.z - mu) * rs, v3 = (vv.w - mu) * rs;
    float mx = fmaxf(fmaxf(fabsf(v0), fabsf(v1)), fmaxf(fabsf(v2), fabsf(v3)));

    sh[threadIdx.x] = mx; __syncthreads();
    for (int o = 128; o > 0; o >>= 1) {
        if (threadIdx.x < o) sh[threadIdx.x] = fmaxf(sh[threadIdx.x], sh[threadIdx.x + o]);
        __syncthreads();
    }
    float maxc  = fmaxf(sh[0], 1e-5f);
    float scale = 127.0f / maxc;

    float q0 = fminf(fmaxf(rintf(v0 * scale), -128.0f), 127.0f);
    float q1 = fminf(fmaxf(rintf(v1 * scale), -128.0f), 127.0f);
    float q2 = fminf(fmaxf(rintf(v2 * scale), -128.0f), 127.0f);
    float q3 = fminf(fmaxf(rintf(v3 * scale), -128.0f), 127.0f);
    __nv_bfloat162* o2 = (__nv_bfloat162*)(op + c0);
    o2[0] = __floats2bfloat162_rn(q0, q1);
    o2[1] = __floats2bfloat162_rn(q2, q3);

    if (threadIdx.x == 0) g_arow[row] = 1.0f / scale;
}

// ---------------- z activation quant (after LN) ----------------
__global__ void k_qact2() {
    int row = blockIdx.x;
    int b = row >> 11;
    float mu = g_zmu[b], rs = g_zrstd[b];
    const float* p = g_Z + (size_t)row * DIM;
    __nv_bfloat16* op = g_A2q + (size_t)row * DIM;

    int c0 = threadIdx.x * 4;
    float4 vv = *(const float4*)(p + c0);
    float v0 = (vv.x - mu) * rs, v1 = (vv.y - mu) * rs;
    float v2 = (vv.z - mu) * rs, v3 = (vv.w - mu) * rs;
    float mx = fmaxf(fmaxf(fabsf(v0), fabsf(v1)), fmaxf(fabsf(v2), fabsf(v3)));

    __shared__ float sh[256];
    sh[threadIdx.x] = mx; __syncthreads();
    for (int o = 128; o > 0; o >>= 1) {
        if (threadIdx.x < o) sh[threadIdx.x] = fmaxf(sh[threadIdx.x], sh[threadIdx.x + o]);
        __syncthreads();
    }
    float maxc  = fmaxf(sh[0], 1e-5f);
    float scale = 127.0f / maxc;

    float q0 = fminf(fmaxf(rintf(v0 * scale), -128.0f), 127.0f);
    float q1 = fminf(fmaxf(rintf(v1 * scale), -128.0f), 127.0f);
    float q2 = fminf(fmaxf(rintf(v2 * scale), -128.0f), 127.0f);
    float q3 = fminf(fmaxf(rintf(v3 * scale), -128.0f), 127.0f);
    __nv_bfloat162* o2 = (__nv_bfloat162*)(op + c0);
    o2[0] = __floats2bfloat162_rn(q0, q1);
    o2[1] = __floats2bfloat162_rn(q2, q3);

    if (threadIdx.x == 0) g_a2row[row] = 1.0f / scale;
}

// ---------------- mma helpers ----------------
__device__ __forceinline__ void ldmx4(uint32_t& r0, uint32_t& r1,
                                      uint32_t& r2, uint32_t& r3, uint32_t addr) {
    asm volatile("ldmatrix.sync.aligned.m8n8.x4.shared.b16 {%0,%1,%2,%3}, [%4];"
        : "=r"(r0), "=r"(r1), "=r"(r2), "=r"(r3) : "r"(addr));
}
__device__ __forceinline__ void ldmx4t(uint32_t& r0, uint32_t& r1,
                                       uint32_t& r2, uint32_t& r3, uint32_t addr) {
    asm volatile("ldmatrix.sync.aligned.m8n8.x4.trans.shared.b16 {%0,%1,%2,%3}, [%4];"
        : "=r"(r0), "=r"(r1), "=r"(r2), "=r"(r3) : "r"(addr));
}
__device__ __forceinline__ void mma16816(float* c, const uint32_t* a,
                                         uint32_t b0, uint32_t b1) {
    asm volatile("mma.sync.aligned.m16n8k16.row.col.f32.bf16.bf16.f32 "
        "{%0,%1,%2,%3},{%4,%5,%6,%7},{%8,%9},{%0,%1,%2,%3};"
        : "+f"(c[0]), "+f"(c[1]), "+f"(c[2]), "+f"(c[3])
        : "r"(a[0]), "r"(a[1]), "r"(a[2]), "r"(a[3]), "r"(b0), "r"(b1));
}
__device__ __forceinline__ uint32_t packbf2(float v0, float v1) {
    __nv_bfloat162 hv;
    hv.x = __float2bfloat16(v0);
    hv.y = __float2bfloat16(v1);
    return *reinterpret_cast<uint32_t*>(&hv);
}

// ---------------- bf16 tensor-core GEMM (exact integers), double-buffered ----------------
#define SPITCH 40
#define BUFB   (128 * SPITCH * 2)

__global__ void __launch_bounds__(256) k_gemm_mma(int baseMode, float* __restrict__ dst) {
    int mode = baseMode + blockIdx.z;
    const __nv_bfloat16* A = (mode == 4) ? g_A2q : g_Aq;
    const float* arow      = (mode == 4) ? g_a2row : g_arow;
    const __nv_bfloat16* W = g_Wt + (size_t)mode * DIM * DIM;

    __shared__ __nv_bfloat16 As[2][128 * SPITCH];
    __shared__ __nv_bfloat16 Bs[2][128 * SPITCH];
    __shared__ float s_wdeq;

    int tid = threadIdx.x;
    int warp = tid >> 5, lane = tid & 31;
    int wm = warp >> 2, wn = warp & 3;

    if (tid == 0) {
        float sc = fin_wsc(mode);
        s_wdeq = 1.0f / sc;      // bit-identical to old wdeq chain
    }

    const __nv_bfloat16* Ag = A + (size_t)blockIdx.y * 128 * DIM;
    const __nv_bfloat16* Wg = W + (size_t)blockIdx.x * 128 * DIM;

    int lr0 = tid >> 2;
    int lc0 = (tid & 3) * 8;

    uint32_t sA0 = (uint32_t)__cvta_generic_to_shared(&As[0][0]);
    uint32_t sB0 = (uint32_t)__cvta_generic_to_shared(&Bs[0][0]);

    int a_row = wm * 64 + (lane & 15);
    int a_col = ((lane >> 4) << 3);
    int b_row = wn * 32 + (lane & 7) + (((lane >> 4) & 1) << 3);
    int b_col = (((lane >> 3) & 1) << 3);

    float c[4][4][4];
    #pragma unroll
    for (int mi = 0; mi < 4; mi++)
        #pragma unroll
        for (int ni = 0; ni < 4; ni++)
            #pragma unroll
            for (int r = 0; r < 4; r++) c[mi][ni][r] = 0.0f;

    {
        uint4 t0 = *(const uint4*)(Ag + (size_t)lr0        * DIM + lc0);
        uint4 t1 = *(const uint4*)(Ag + (size_t)(lr0 + 64) * DIM + lc0);
        uint4 t2 = *(const uint4*)(Wg + (size_t)lr0        * DIM + lc0);
        uint4 t3 = *(const uint4*)(Wg + (size_t)(lr0 + 64) * DIM + lc0);
        *(uint4*)&As[0][lr0 * SPITCH + lc0]        = t0;
        *(uint4*)&As[0][(lr0 + 64) * SPITCH + lc0] = t1;
        *(uint4*)&Bs[0][lr0 * SPITCH + lc0]        = t2;
        *(uint4*)&Bs[0][(lr0 + 64) * SPITCH + lc0] = t3;
    }
    uint4 ra0 = *(const uint4*)(Ag + (size_t)lr0        * DIM + 32 + lc0);
    uint4 ra1 = *(const uint4*)(Ag + (size_t)(lr0 + 64) * DIM + 32 + lc0);
    uint4 rb0 = *(const uint4*)(Wg + (size_t)lr0        * DIM + 32 + lc0);
    uint4 rb1 = *(const uint4*)(Wg + (size_t)(lr0 + 64) * DIM + 32 + lc0);
    __syncthreads();

    for (int kt = 0; kt < 32; ++kt) {
        int cur = kt & 1;
        int nxt = cur ^ 1;

        if (kt < 31) {
            *(uint4*)&As[nxt][lr0 * SPITCH + lc0]        = ra0;
            *(uint4*)&As[nxt][(lr0 + 64) * SPITCH + lc0] = ra1;
            *(uint4*)&Bs[nxt][lr0 * SPITCH + lc0]        = rb0;
            *(uint4*)&Bs[nxt][(lr0 + 64) * SPITCH + lc0] = rb1;
        }
        if (kt < 30) {
            int kc = (kt + 2) * 32 + lc0;
            ra0 = *(const uint4*)(Ag + (size_t)lr0        * DIM + kc);
            ra1 = *(const uint4*)(Ag + (size_t)(lr0 + 64) * DIM + kc);
            rb0 = *(const uint4*)(Wg + (size_t)lr0        * DIM + kc);
            rb1 = *(const uint4*)(Wg + (size_t)(lr0 + 64) * DIM + kc);
        }

        uint32_t bA = sA0 + (uint32_t)cur * BUFB;
        uint32_t bB = sB0 + (uint32_t)cur * BUFB;

        #pragma unroll
        for (int kk = 0; kk < 2; ++kk) {
            uint32_t afr[4][4], bfr[2][4];
            #pragma unroll
            for (int mi = 0; mi < 4; mi++) {
                uint32_t smaddr = bA + (uint32_t)((a_row + mi * 16) * SPITCH + kk * 16 + a_col) * 2u;
                ldmx4(afr[mi][0], afr[mi][1], afr[mi][2], afr[mi][3], smaddr);
            }
            #pragma unroll
            for (int p = 0; p < 2; p++) {
                uint32_t smaddr = bB + (uint32_t)((b_row + p * 16) * SPITCH + kk * 16 + b_col) * 2u;
                ldmx4(bfr[p][0], bfr[p][1], bfr[p][2], bfr[p][3], smaddr);
            }
            #pragma unroll
            for (int mi = 0; mi < 4; mi++)
                #pragma unroll
                for (int ni = 0; ni < 4; ni++)
                    mma16816(c[mi][ni], afr[mi],
                             bfr[ni >> 1][(ni & 1) * 2], bfr[ni >> 1][(ni & 1) * 2 + 1]);
        }
        __syncthreads();
    }

    float wsc = s_wdeq;
    int m_base = blockIdx.y * 128 + wm * 64;
    int n_base = blockIdx.x * 128 + wn * 32;
    int lr = lane >> 2;
    int lc = (lane & 3) * 2;

    #pragma unroll
    for (int mi = 0; mi < 4; mi++) {
        #pragma unroll
        for (int rr = 0; rr < 2; rr++) {
            int m = m_base + mi * 16 + rr * 8 + lr;
            float sc = arow[m] * wsc;
            if (mode <= 2) {
                __nv_bfloat16* hp = (mode == 0) ? g_Qh : (mode == 1) ? g_Kh : g_Vh;
                __nv_bfloat16* lp = (mode == 0) ? g_Ql : (mode == 1) ? g_Kl : g_Vl;
                float sce = (mode == 0) ? sc * 0.125f : sc;
                int bb = m >> 11, ns = m & 2047;
                #pragma unroll
                for (int ni = 0; ni < 4; ni++) {
                    int n = n_base + ni * 8 + lc;
                    int hh = n >> 6, dd = n & 63;
                    float v0 = c[mi][ni][rr * 2 + 0] * sce;
                    float v1 = c[mi][ni][rr * 2 + 1] * sce;
                    __nv_bfloat16 h0 = __float2bfloat16(v0);
                    __nv_bfloat16 h1 = __float2bfloat16(v1);
                    float l0 = v0 - __bfloat162float(h0);
                    float l1 = v1 - __bfloat162float(h1);
                    size_t idx = (((size_t)(bb * NH + hh)) * NSEQ + ns) * HD + dd;
                    __nv_bfloat162 hv; hv.x = h0; hv.y = h1;
                    __nv_bfloat162 lv; lv.x = __float2bfloat16(l0); lv.y = __float2bfloat16(l1);
                    *(__nv_bfloat162*)&hp[idx] = hv;
                    *(__nv_bfloat162*)&lp[idx] = lv;
                }
            } else if (mode == 3) {
                #pragma unroll
                for (int ni = 0; ni < 4; ni++) {
                    int n = n_base + ni * 8 + lc;
                    float v0 = c[mi][ni][rr * 2 + 0] * sc;
                    float v1 = c[mi][ni][rr * 2 + 1] * sc;
                    float2 o;
                    o.x = v0 / (1.0f + expf(-v0));
                    o.y = v1 / (1.0f + expf(-v1));
                    *(float2*)&g_G[(size_t)m * DIM + n] = o;
                }
            } else {
                #pragma unroll
                for (int ni = 0; ni < 4; ni++) {
                    int n = n_base + ni * 8 + lc;
                    float2 o;
                    o.x = c[mi][ni][rr * 2 + 0] * sc;
                    o.y = c[mi][ni][rr * 2 + 1] * sc;
                    *(float2*)&dst[(size_t)m * DIM + n] = o;
                }
            }
        }
    }
}

// ---------------- attention: register-resident S + smem decay window ----------------
#define BP 72
#define ATT_TILE (64 * BP)
#define ATT_SMEM (6 * ATT_TILE * 2 + 512)

__global__ void __launch_bounds__(256) k_attn_mma() {
    extern __shared__ __nv_bfloat16 dyn[];
    __nv_bfloat16 *sQh = dyn,                *sQl = dyn + ATT_TILE;
    __nv_bfloat16 *sKh = dyn + 2 * ATT_TILE, *sKl = dyn + 3 * ATT_TILE;
    __nv_bfloat16 *sVh = dyn + 4 * ATT_TILE, *sVl = dyn + 5 * ATT_TILE;
    float* sdec = (float*)(dyn + 6 * ATT_TILE);
    float* red = (float*)(dyn + 2 * ATT_TILE);   // overlays K after main loop

    int nt = (NSEQ / 64 - 1) - blockIdx.x;
    int h = blockIdx.y, b = blockIdx.z;
    int n0 = nt * 64;
    size_t base = ((size_t)(b * NH + h)) * NSEQ * HD;
    const __nv_bfloat16 *Qhp = g_Qh + base, *Qlp = g_Ql + base;
    const __nv_bfloat16 *Khp = g_Kh + base, *Klp = g_Kl + base;
    const __nv_bfloat16 *Vhp = g_Vh + base, *Vlp = g_Vl + base;

    // per-head decay constants (double, once per block per thread)
    double lina = log(1.0 / 32.0), linb = log(1.0 / 512.0);
    double lin = lina + (linb - lina) * ((double)h / 15.0);
    double gamma = 1.0 - exp(lin);
    double lg = log(gamma);
    float l2gf = (float)(lg * 1.4426950408889634);
    int dcut = (int)(13.815510557964274 / (-lg)) + 1;

    int tid = threadIdx.x;
    int warp = tid >> 5, lane = tid & 31;
    int wm = warp & 3, wn = warp >> 2;

    uint32_t aQh = (uint32_t)__cvta_generic_to_shared(sQh);
    uint32_t aQl = (uint32_t)__cvta_generic_to_shared(sQl);
    uint32_t aKh = (uint32_t)__cvta_generic_to_shared(sKh);
    uint32_t aKl = (uint32_t)__cvta_generic_to_shared(sKl);
    uint32_t aVh = (uint32_t)__cvta_generic_to_shared(sVh);
    uint32_t aVl = (uint32_t)__cvta_generic_to_shared(sVl);

    for (int j = tid; j < 512; j += 256) {
        int r = j >> 3, c8 = (j & 7) * 8;
        *(uint4*)&sQh[r * BP + c8] = *(const uint4*)(Qhp + (size_t)(n0 + r) * HD + c8);
        *(uint4*)&sQl[r * BP + c8] = *(const uint4*)(Qlp + (size_t)(n0 + r) * HD + c8);
    }

    int a_row = wm * 16 + (lane & 15);
    int a_sel = (lane >> 4) << 3;
    int bq_row = wn * 32 + (lane & 7) + (((lane >> 4) & 1) << 3);
    int bq_col = ((lane >> 3) & 1) << 3;
    int bv_row = lane & 15;
    int bv_sel = ((lane >> 4) & 1) << 3;
    int lr = lane >> 2, lc2 = (lane & 3) * 2;

    float yacc[8][4];
    #pragma unroll
    for (int i = 0; i < 8; i++)
        #pragma unroll
        for (int r = 0; r < 4; r++) yacc[i][r] = 0.0f;

    int lim = n0 - 63 - dcut;
    int mt0 = (lim > 0) ? ((lim + 63) >> 6) : 0;

    for (int mt = mt0; mt <= nt; ++mt) {
        int m0 = mt * 64;
        __syncthreads();
        for (int j = tid; j < 512; j += 256) {
            int r = j >> 3, c8 = (j & 7) * 8;
            *(uint4*)&sKh[r * BP + c8] = *(const uint4*)(Khp + (size_t)(m0 + r) * HD + c8);
            *(uint4*)&sKl[r * BP + c8] = *(const uint4*)(Klp + (size_t)(m0 + r) * HD + c8);
            *(uint4*)&sVh[r * BP + c8] = *(const uint4*)(Vhp + (size_t)(m0 + r) * HD + c8);
            *(uint4*)&sVl[r * BP + c8] = *(const uint4*)(Vlp + (size_t)(m0 + r) * HD + c8);
        }
        if (tid < 128) {
            int d = (n0 - m0) - 64 + tid;
            sdec[tid] = (d >= 0) ? exp2f((float)d * l2gf) : 0.0f;
        }
        __syncthreads();

        // ---- S = Q K^T (3-term hi/lo) ----
        float sacc[4][4];
        #pragma unroll
        for (int ni = 0; ni < 4; ni++)
            #pragma unroll
            for (int r = 0; r < 4; r++) sacc[ni][r] = 0.0f;

        #pragma unroll
        for (int ks = 0; ks < 4; ks++) {
            uint32_t ah[4], al[4], bh[2][4], bl[2][4];
            uint32_t aoff = (uint32_t)(a_row * BP + ks * 16 + a_sel) * 2u;
            ldmx4(ah[0], ah[1], ah[2], ah[3], aQh + aoff);
            ldmx4(al[0], al[1], al[2], al[3], aQl + aoff);
            #pragma unroll
            for (int p = 0; p < 2; p++) {
                uint32_t boff = (uint32_t)((bq_row + p * 16) * BP + ks * 16 + bq_col) * 2u;
                ldmx4(bh[p][0], bh[p][1], bh[p][2], bh[p][3], aKh + boff);
                ldmx4(bl[p][0], bl[p][1], bl[p][2], bl[p][3], aKl + boff);
            }
            #pragma unroll
            for (int ni = 0; ni < 4; ni++) {
                int p = ni >> 1, q2 = (ni & 1) * 2;
                mma16816(sacc[ni], ah, bh[p][q2], bh[p][q2 + 1]);
                mma16816(sacc[ni], ah, bl[p][q2], bl[p][q2 + 1]);
                mma16816(sacc[ni], al, bh[p][q2], bh[p][q2 + 1]);
            }
        }

        // ---- decay (smem window, branch-free) + hi/lo split, C-frag -> A-frag ----
        uint32_t shf[2][4], slf[2][4];
        #pragma unroll
        for (int ni = 0; ni < 4; ni++) {
            int col0 = wn * 32 + ni * 8 + lc2;
            #pragma unroll
            for (int half = 0; half < 2; half++) {
                int row = wm * 16 + lr + half * 8;
                int widx = row - col0 + 64;
                float v0 = sacc[ni][half * 2 + 0] * sdec[widx];
                float v1 = sacc[ni][half * 2 + 1] * sdec[widx - 1];
                uint32_t hr = packbf2(v0, v1);
                __nv_bfloat162 hb = *reinterpret_cast<__nv_bfloat162*>(&hr);
                float l0 = v0 - __bfloat162float(hb.x);
                float l1 = v1 - __bfloat162float(hb.y);
                shf[ni >> 1][(ni & 1) * 2 + half] = hr;
                slf[ni >> 1][(ni & 1) * 2 + half] = packbf2(l0, l1);
            }
        }

        // ---- Y_partial += S V ----
        #pragma unroll
        for (int ks2 = 0; ks2 < 2; ks2++) {
            #pragma unroll
            for (int t = 0; t < 4; t++) {
                uint32_t bh[4], bl[4];
                uint32_t voff = (uint32_t)((wn * 32 + ks2 * 16 + bv_row) * BP
                                           + t * 16 + bv_sel) * 2u;
                ldmx4t(bh[0], bh[1], bh[2], bh[3], aVh + voff);
                ldmx4t(bl[0], bl[1], bl[2], bl[3], aVl + voff);
                #pragma unroll
                for (int j = 0; j < 2; j++) {
                    mma16816(yacc[t * 2 + j], shf[ks2], bh[j * 2], bh[j * 2 + 1]);
                    mma16816(yacc[t * 2 + j], shf[ks2], bl[j * 2], bl[j * 2 + 1]);
                    mma16816(yacc[t * 2 + j], slf[ks2], bh[j * 2], bh[j * 2 + 1]);
                }
            }
        }
    }

    // ---- merge wn halves via smem ----
    __syncthreads();
    if (wn == 1) {
        #pragma unroll
        for (int d8 = 0; d8 < 8; d8++)
            #pragma unroll
            for (int r = 0; r < 4; r++) {
                int row = wm * 16 + lr + (r >> 1) * 8;
                int dd = d8 * 8 + lc2 + (r & 1);
                red[row * 64 + dd] = yacc[d8][r];
            }
    }
    __syncthreads();
    if (wn == 0) {
        #pragma unroll
        for (int d8 = 0; d8 < 8; d8++)
            #pragma unroll
            for (int half = 0; half < 2; half++) {
                int row = wm * 16 + lr + half * 8;
                int dd = d8 * 8 + lc2;
                float2 o;
                o.x = yacc[d8][half * 2 + 0] + red[row * 64 + dd];
                o.y = yacc[d8][half * 2 + 1] + red[row * 64 + dd + 1];
                *(float2*)&g_Y[(size_t)(b * NSEQ + n0 + row) * DIM + h * HD + dd] = o;
            }
    }
}

// ---------------- LN(y)*silu(g) + per-row double partials ----------------
__global__ void k_lng(const float* __restrict__ lnw, const float* __restrict__ lnb) {
    int row = blockIdx.x;
    const float* y = g_Y + (size_t)row * DIM;
    int c0 = threadIdx.x * 4;
    float4 yv = *(const float4*)(y + c0);

    __shared__ double shs[256], shq[256];
    shs[threadIdx.x] = (double)yv.x + yv.y + yv.z + yv.w;
    shq[threadIdx.x] = (double)yv.x*yv.x + (double)yv.y*yv.y
                     + (double)yv.z*yv.z + (double)yv.w*yv.w;
    __syncthreads();
    for (int o = 128; o > 0; o >>= 1) {
        if (threadIdx.x < o) {
            shs[threadIdx.x] += shs[threadIdx.x + o];
            shq[threadIdx.x] += shq[threadIdx.x + o];
        }
        __syncthreads();
    }
    double mu_d  = shs[0] / (double)DIM;
    double var_d = shq[0] / (double)DIM - mu_d * mu_d;
    float mu = (float)mu_d;
    float rs = (float)(1.0 / sqrt(var_d + 1e-5));
    __syncthreads();

    float4 g4 = *(const float4*)(g_G + (size_t)row * DIM + c0);
    float4 w4 = *(const float4*)(lnw + c0);
    float4 b4 = *(const float4*)(lnb + c0);
    float4 z;
    z.x = ((yv.x - mu) * rs * w4.x + b4.x) * g4.x;
    z.y = ((yv.y - mu) * rs * w4.y + b4.y) * g4.y;
    z.z = ((yv.z - mu) * rs * w4.z + b4.z) * g4.z;
    z.w = ((yv.w - mu) * rs * w4.w + b4.w) * g4.w;
    *(float4*)&g_Z[(size_t)row * DIM + c0] = z;

    shs[threadIdx.x] = (double)z.x + z.y + z.z + z.w;
    shq[threadIdx.x] = (double)z.x*z.x + (double)z.y*z.y
                     + (double)z.z*z.z + (double)z.w*z.w;
    __syncthreads();
    for (int o = 128; o > 0; o >>= 1) {
        if (threadIdx.x < o) {
            shs[threadIdx.x] += shs[threadIdx.x + o];
            shq[threadIdx.x] += shq[threadIdx.x + o];
        }
        __syncthreads();
    }
    if (threadIdx.x == 0) {
        g_zpart_s[row] = shs[0];
        g_zpart_q[row] = shq[0];
    }
}

__global__ void k_fin2() {
    int b = blockIdx.x;
    double s = 0.0, q = 0.0;
    for (int i = threadIdx.x; i < NSEQ; i += 256) {
        s += g_zpart_s[b * NSEQ + i];
        q += g_zpart_q[b * NSEQ + i];
    }
    __shared__ double shs[256], shq[256];
    shs[threadIdx.x] = s; shq[threadIdx.x] = q; __syncthreads();
    for (int o = 128; o > 0; o >>= 1) {
        if (threadIdx.x < o) {
            shs[threadIdx.x] += shs[threadIdx.x + o];
            shq[threadIdx.x] += shq[threadIdx.x + o];
        }
        __syncthreads();
    }
    if (threadIdx.x == 0) {
        double n = (double)BELEMS;
        double mu = shs[0] / n;
        double var = shq[0] / n - mu * mu;
        g_zmu[b]   = (float)mu;
        g_zrstd[b] = (float)(1.0 / sqrt(var + 1e-5));
    }
}

// ---------------- launch ----------------
extern "C" void kernel_launch(void* const* d_in, const int* in_sizes, int n_in,
                              void* d_out, int out_size) {
    (void)in_sizes; (void)n_in; (void)out_size;
    const float* x   = (const float*)d_in[0];
    const float* wq  = (const float*)d_in[1];
    const float* wk  = (const float*)d_in[2];
    const float* wv  = (const float*)d_in[3];
    const float* wg  = (const float*)d_in[4];
    const float* wo  = (const float*)d_in[5];
    const float* lnw = (const float*)d_in[6];
    const float* lnb = (const float*)d_in[7];
    float* out = (float*)d_out;

    cudaFuncSetAttribute(k_attn_mma,
                         cudaFuncAttributeMaxDynamicSharedMemorySize, ATT_SMEM);

    k_reduce_all <<<dim3(64, 7),     256>>>(x, wq, wk, wv, wg, wo);   // 1
    k_prep       <<<dim3(4096, 6),   256>>>(x, wq, wk, wv, wg, wo);   // 2
    k_gemm_mma   <<<dim3(8, 32, 4),  256>>>(0, out);                  // 3
    k_attn_mma   <<<dim3(NSEQ/64, NH, BATCH), 256, ATT_SMEM>>>();     // 4 <- profiled
    k_lng        <<<ROWS, 256>>>(lnw, lnb);                           // 5
    k_fin2       <<<BATCH, 256>>>();                                  // 6
    k_qact2      <<<ROWS, 256>>>();                                   // 7
    k_gemm_mma   <<<dim3(8, 32, 1),  256>>>(4, out);                  // 8
}

// round 16
// speedup vs baseline: 1.1703x; 1.1703x over previous
#include <cuda_runtime.h>
#include <cuda_bf16.h>
#include <cstdint>
#include <stdint.h>
#include <math.h>

#define BATCH 2
#define NSEQ 2048
#define DIM 1024
#define NH 16
#define HD 64
#define ROWS (BATCH*NSEQ)          // 4096
#define BELEMS (NSEQ*DIM)          // 2097152

// ---------------- device scratch ----------------
__device__ double g_xpart_s[BATCH*64], g_xpart_q[BATCH*64];
__device__ double g_wpart[5*64];
__device__ double g_zpart_s[ROWS], g_zpart_q[ROWS];
__device__ float  g_xmu[BATCH], g_xrstd[BATCH];
__device__ float  g_zmu[BATCH], g_zrstd[BATCH];
__device__ float  g_wsc[5];
__device__ float  g_wdeq[5];
__device__ __nv_bfloat16 g_Aq [ROWS*DIM];
__device__ __nv_bfloat16 g_A2q[ROWS*DIM];
__device__ float  g_arow [ROWS];
__device__ float  g_a2row[ROWS];
__device__ __nv_bfloat16 g_Wt[5*DIM*DIM];
__device__ __nv_bfloat16 g_Qh[BATCH*NH*NSEQ*HD], g_Ql[BATCH*NH*NSEQ*HD];
__device__ __nv_bfloat16 g_Kh[BATCH*NH*NSEQ*HD], g_Kl[BATCH*NH*NSEQ*HD];
__device__ __nv_bfloat16 g_Vh[BATCH*NH*NSEQ*HD], g_Vl[BATCH*NH*NSEQ*HD];
__device__ float  g_G [ROWS*DIM];
__device__ float  g_Y [ROWS*DIM];
__device__ float  g_Z [ROWS*DIM];

// ---------------- fused reductions ----------------
__global__ void k_reduce_all(const float* __restrict__ x,
                             const float* wa, const float* wb, const float* wc,
                             const float* wd, const float* we) {
    int y = blockIdx.y;
    __shared__ double shs[256], shq[256];
    if (y < BATCH) {
        const float* p = x + (size_t)y * BELEMS;
        double s = 0.0, q = 0.0;
        for (int i = blockIdx.x * blockDim.x + threadIdx.x; i < BELEMS;
             i += gridDim.x * blockDim.x) {
            double v = (double)p[i];
            s += v; q += v * v;
        }
        shs[threadIdx.x] = s; shq[threadIdx.x] = q; __syncthreads();
        for (int o = 128; o > 0; o >>= 1) {
            if (threadIdx.x < o) {
                shs[threadIdx.x] += shs[threadIdx.x + o];
                shq[threadIdx.x] += shq[threadIdx.x + o];
            }
            __syncthreads();
        }
        if (threadIdx.x == 0) {
            g_xpart_s[y * 64 + blockIdx.x] = shs[0];
            g_xpart_q[y * 64 + blockIdx.x] = shq[0];
        }
    } else {
        const float* ws[5] = {wa, wb, wc, wd, we};
        const float* w = ws[y - 2];
        double s = 0.0;
        for (int i = blockIdx.x * blockDim.x + threadIdx.x; i < DIM * DIM;
             i += gridDim.x * blockDim.x)
            s += (double)fabsf(w[i]);
        shs[threadIdx.x] = s; __syncthreads();
        for (int o = 128; o > 0; o >>= 1) {
            if (threadIdx.x < o) shs[threadIdx.x] += shs[threadIdx.x + o];
            __syncthreads();
        }
        if (threadIdx.x == 0) g_wpart[(y - 2) * 64 + blockIdx.x] = shs[0];
    }
}

__global__ void k_fin1() {
    int t = threadIdx.x;
    if (t < BATCH) {
        double s = 0.0, q = 0.0;
        for (int i = 0; i < 64; i++) { s += g_xpart_s[t*64+i]; q += g_xpart_q[t*64+i]; }
        double n = (double)BELEMS;
        double mu = s / n;
        double var = q / n - mu * mu;
        g_xmu[t]   = (float)mu;
        g_xrstd[t] = (float)(1.0 / sqrt(var + 1e-5));
    }
    if (t >= 8 && t < 13) {
        int wi = t - 8;
        double s = 0.0;
        for (int i = 0; i < 64; i++) s += g_wpart[wi*64+i];
        float m = (float)(s / (double)(DIM * DIM));
        if (m < 1e-5f) m = 1e-5f;
        float sc = 1.0f / m;
        g_wsc[wi]  = sc;
        g_wdeq[wi] = 1.0f / sc;
    }
}

// ---------------- fused prep: y<5 ternarize weight y, y==5 quantize x acts ----------------
__global__ void k_prep(const float* __restrict__ x,
                       const float* wa, const float* wb, const float* wc,
                       const float* wd, const float* we) {
    int y = blockIdx.y;
    if (y < 5) {
        const float* ws[5] = {wa, wb, wc, wd, we};
        const float* w = ws[y];
        float sc = g_wsc[y];
        __nv_bfloat16* out = g_Wt + (size_t)y * DIM * DIM;
        for (int i = blockIdx.x * blockDim.x + threadIdx.x; i < DIM * DIM / 4;
             i += gridDim.x * blockDim.x) {
            float4 v = *(const float4*)(w + i * 4);
            float t0 = fminf(fmaxf(rintf(v.x * sc), -1.0f), 1.0f);
            float t1 = fminf(fmaxf(rintf(v.y * sc), -1.0f), 1.0f);
            float t2 = fminf(fmaxf(rintf(v.z * sc), -1.0f), 1.0f);
            float t3 = fminf(fmaxf(rintf(v.w * sc), -1.0f), 1.0f);
            __nv_bfloat162* o2 = (__nv_bfloat162*)(out + i * 4);
            o2[0] = __floats2bfloat162_rn(t0, t1);
            o2[1] = __floats2bfloat162_rn(t2, t3);
        }
        return;
    }
    // activation quant of x
    int row = blockIdx.x;
    int b = row >> 11;
    float mu = g_xmu[b], rs = g_xrstd[b];
    const float* p = x + (size_t)row * DIM;
    __nv_bfloat16* op = g_Aq + (size_t)row * DIM;

    int c0 = threadIdx.x * 4;
    float4 vv = *(const float4*)(p + c0);
    float v0 = (vv.x - mu) * rs, v1 = (vv.y - mu) * rs;
    float v2 = (vv.z - mu) * rs, v3 = (vv.w - mu) * rs;
    float mx = fmaxf(fmaxf(fabsf(v0), fabsf(v1)), fmaxf(fabsf(v2), fabsf(v3)));

    __shared__ float sh[256];
    sh[threadIdx.x] = mx; __syncthreads();
    for (int o = 128; o > 0; o >>= 1) {
        if (threadIdx.x < o) sh[threadIdx.x] = fmaxf(sh[threadIdx.x], sh[threadIdx.x + o]);
        __syncthreads();
    }
    float maxc  = fmaxf(sh[0], 1e-5f);
    float scale = 127.0f / maxc;

    float q0 = fminf(fmaxf(rintf(v0 * scale), -128.0f), 127.0f);
    float q1 = fminf(fmaxf(rintf(v1 * scale), -128.0f), 127.0f);
    float q2 = fminf(fmaxf(rintf(v2 * scale), -128.0f), 127.0f);
    float q3 = fminf(fmaxf(rintf(v3 * scale), -128.0f), 127.0f);
    __nv_bfloat162* o2 = (__nv_bfloat162*)(op + c0);
    o2[0] = __floats2bfloat162_rn(q0, q1);
    o2[1] = __floats2bfloat162_rn(q2, q3);

    if (threadIdx.x == 0) g_arow[row] = 1.0f / scale;
}

// ---------------- z activation quant (after LN) ----------------
__global__ void k_qact2() {
    int row = blockIdx.x;
    int b = row >> 11;
    float mu = g_zmu[b], rs = g_zrstd[b];
    const float* p = g_Z + (size_t)row * DIM;
    __nv_bfloat16* op = g_A2q + (size_t)row * DIM;

    int c0 = threadIdx.x * 4;
    float4 vv = *(const float4*)(p + c0);
    float v0 = (vv.x - mu) * rs, v1 = (vv.y - mu) * rs;
    float v2 = (vv.z - mu) * rs, v3 = (vv.w - mu) * rs;
    float mx = fmaxf(fmaxf(fabsf(v0), fabsf(v1)), fmaxf(fabsf(v2), fabsf(v3)));

    __shared__ float sh[256];
    sh[threadIdx.x] = mx; __syncthreads();
    for (int o = 128; o > 0; o >>= 1) {
        if (threadIdx.x < o) sh[threadIdx.x] = fmaxf(sh[threadIdx.x], sh[threadIdx.x + o]);
        __syncthreads();
    }
    float maxc  = fmaxf(sh[0], 1e-5f);
    float scale = 127.0f / maxc;

    float q0 = fminf(fmaxf(rintf(v0 * scale), -128.0f), 127.0f);
    float q1 = fminf(fmaxf(rintf(v1 * scale), -128.0f), 127.0f);
    float q2 = fminf(fmaxf(rintf(v2 * scale), -128.0f), 127.0f);
    float q3 = fminf(fmaxf(rintf(v3 * scale), -128.0f), 127.0f);
    __nv_bfloat162* o2 = (__nv_bfloat162*)(op + c0);
    o2[0] = __floats2bfloat162_rn(q0, q1);
    o2[1] = __floats2bfloat162_rn(q2, q3);

    if (threadIdx.x == 0) g_a2row[row] = 1.0f / scale;
}

// ---------------- mma helpers ----------------
__device__ __forceinline__ void ldmx4(uint32_t& r0, uint32_t& r1,
                                      uint32_t& r2, uint32_t& r3, uint32_t addr) {
    asm volatile("ldmatrix.sync.aligned.m8n8.x4.shared.b16 {%0,%1,%2,%3}, [%4];"
        : "=r"(r0), "=r"(r1), "=r"(r2), "=r"(r3) : "r"(addr));
}
__device__ __forceinline__ void ldmx4t(uint32_t& r0, uint32_t& r1,
                                       uint32_t& r2, uint32_t& r3, uint32_t addr) {
    asm volatile("ldmatrix.sync.aligned.m8n8.x4.trans.shared.b16 {%0,%1,%2,%3}, [%4];"
        : "=r"(r0), "=r"(r1), "=r"(r2), "=r"(r3) : "r"(addr));
}
__device__ __forceinline__ void mma16816(float* c, const uint32_t* a,
                                         uint32_t b0, uint32_t b1) {
    asm volatile("mma.sync.aligned.m16n8k16.row.col.f32.bf16.bf16.f32 "
        "{%0,%1,%2,%3},{%4,%5,%6,%7},{%8,%9},{%0,%1,%2,%3};"
        : "+f"(c[0]), "+f"(c[1]), "+f"(c[2]), "+f"(c[3])
        : "r"(a[0]), "r"(a[1]), "r"(a[2]), "r"(a[3]), "r"(b0), "r"(b1));
}
__device__ __forceinline__ uint32_t packbf2(float v0, float v1) {
    __nv_bfloat162 hv;
    hv.x = __float2bfloat16(v0);
    hv.y = __float2bfloat16(v1);
    return *reinterpret_cast<uint32_t*>(&hv);
}

// ---------------- bf16 tensor-core GEMM (exact integers), double-buffered ----------------
#define SPITCH 40
#define BUFB   (128 * SPITCH * 2)

__global__ void __launch_bounds__(256) k_gemm_mma(int baseMode, float* __restrict__ dst) {
    int mode = baseMode + blockIdx.z;
    const __nv_bfloat16* A = (mode == 4) ? g_A2q : g_Aq;
    const float* arow      = (mode == 4) ? g_a2row : g_arow;
    const __nv_bfloat16* W = g_Wt + (size_t)mode * DIM * DIM;
    float wsc = g_wdeq[mode];

    __shared__ __nv_bfloat16 As[2][128 * SPITCH];
    __shared__ __nv_bfloat16 Bs[2][128 * SPITCH];

    int tid = threadIdx.x;
    int warp = tid >> 5, lane = tid & 31;
    int wm = warp >> 2, wn = warp & 3;

    const __nv_bfloat16* Ag = A + (size_t)blockIdx.y * 128 * DIM;
    const __nv_bfloat16* Wg = W + (size_t)blockIdx.x * 128 * DIM;

    int lr0 = tid >> 2;
    int lc0 = (tid & 3) * 8;

    uint32_t sA0 = (uint32_t)__cvta_generic_to_shared(&As[0][0]);
    uint32_t sB0 = (uint32_t)__cvta_generic_to_shared(&Bs[0][0]);

    int a_row = wm * 64 + (lane & 15);
    int a_col = ((lane >> 4) << 3);
    int b_row = wn * 32 + (lane & 7) + (((lane >> 4) & 1) << 3);
    int b_col = (((lane >> 3) & 1) << 3);

    float c[4][4][4];
    #pragma unroll
    for (int mi = 0; mi < 4; mi++)
        #pragma unroll
        for (int ni = 0; ni < 4; ni++)
            #pragma unroll
            for (int r = 0; r < 4; r++) c[mi][ni][r] = 0.0f;

    {
        uint4 t0 = *(const uint4*)(Ag + (size_t)lr0        * DIM + lc0);
        uint4 t1 = *(const uint4*)(Ag + (size_t)(lr0 + 64) * DIM + lc0);
        uint4 t2 = *(const uint4*)(Wg + (size_t)lr0        * DIM + lc0);
        uint4 t3 = *(const uint4*)(Wg + (size_t)(lr0 + 64) * DIM + lc0);
        *(uint4*)&As[0][lr0 * SPITCH + lc0]        = t0;
        *(uint4*)&As[0][(lr0 + 64) * SPITCH + lc0] = t1;
        *(uint4*)&Bs[0][lr0 * SPITCH + lc0]        = t2;
        *(uint4*)&Bs[0][(lr0 + 64) * SPITCH + lc0] = t3;
    }
    uint4 ra0 = *(const uint4*)(Ag + (size_t)lr0        * DIM + 32 + lc0);
    uint4 ra1 = *(const uint4*)(Ag + (size_t)(lr0 + 64) * DIM + 32 + lc0);
    uint4 rb0 = *(const uint4*)(Wg + (size_t)lr0        * DIM + 32 + lc0);
    uint4 rb1 = *(const uint4*)(Wg + (size_t)(lr0 + 64) * DIM + 32 + lc0);
    __syncthreads();

    for (int kt = 0; kt < 32; ++kt) {
        int cur = kt & 1;
        int nxt = cur ^ 1;

        if (kt < 31) {
            *(uint4*)&As[nxt][lr0 * SPITCH + lc0]        = ra0;
            *(uint4*)&As[nxt][(lr0 + 64) * SPITCH + lc0] = ra1;
            *(uint4*)&Bs[nxt][lr0 * SPITCH + lc0]        = rb0;
            *(uint4*)&Bs[nxt][(lr0 + 64) * SPITCH + lc0] = rb1;
        }
        if (kt < 30) {
            int kc = (kt + 2) * 32 + lc0;
            ra0 = *(const uint4*)(Ag + (size_t)lr0        * DIM + kc);
            ra1 = *(const uint4*)(Ag + (size_t)(lr0 + 64) * DIM + kc);
            rb0 = *(const uint4*)(Wg + (size_t)lr0        * DIM + kc);
            rb1 = *(const uint4*)(Wg + (size_t)(lr0 + 64) * DIM + kc);
        }

        uint32_t bA = sA0 + (uint32_t)cur * BUFB;
        uint32_t bB = sB0 + (uint32_t)cur * BUFB;

        #pragma unroll
        for (int kk = 0; kk < 2; ++kk) {
            uint32_t afr[4][4], bfr[2][4];
            #pragma unroll
            for (int mi = 0; mi < 4; mi++) {
                uint32_t smaddr = bA + (uint32_t)((a_row + mi * 16) * SPITCH + kk * 16 + a_col) * 2u;
                ldmx4(afr[mi][0], afr[mi][1], afr[mi][2], afr[mi][3], smaddr);
            }
            #pragma unroll
            for (int p = 0; p < 2; p++) {
                uint32_t smaddr = bB + (uint32_t)((b_row + p * 16) * SPITCH + kk * 16 + b_col) * 2u;
                ldmx4(bfr[p][0], bfr[p][1], bfr[p][2], bfr[p][3], smaddr);
            }
            #pragma unroll
            for (int mi = 0; mi < 4; mi++)
                #pragma unroll
                for (int ni = 0; ni < 4; ni++)
                    mma16816(c[mi][ni], afr[mi],
                             bfr[ni >> 1][(ni & 1) * 2], bfr[ni >> 1][(ni & 1) * 2 + 1]);
        }
        __syncthreads();
    }

    int m_base = blockIdx.y * 128 + wm * 64;
    int n_base = blockIdx.x * 128 + wn * 32;
    int lr = lane >> 2;
    int lc = (lane & 3) * 2;

    #pragma unroll
    for (int mi = 0; mi < 4; mi++) {
        #pragma unroll
        for (int rr = 0; rr < 2; rr++) {
            int m = m_base + mi * 16 + rr * 8 + lr;
            float sc = arow[m] * wsc;
            if (mode <= 2) {
                __nv_bfloat16* hp = (mode == 0) ? g_Qh : (mode == 1) ? g_Kh : g_Vh;
                __nv_bfloat16* lp = (mode == 0) ? g_Ql : (mode == 1) ? g_Kl : g_Vl;
                float sce = (mode == 0) ? sc * 0.125f : sc;
                int bb = m >> 11, ns = m & 2047;
                #pragma unroll
                for (int ni = 0; ni < 4; ni++) {
                    int n = n_base + ni * 8 + lc;
                    int hh = n >> 6, dd = n & 63;
                    float v0 = c[mi][ni][rr * 2 + 0] * sce;
                    float v1 = c[mi][ni][rr * 2 + 1] * sce;
                    __nv_bfloat16 h0 = __float2bfloat16(v0);
                    __nv_bfloat16 h1 = __float2bfloat16(v1);
                    float l0 = v0 - __bfloat162float(h0);
                    float l1 = v1 - __bfloat162float(h1);
                    size_t idx = (((size_t)(bb * NH + hh)) * NSEQ + ns) * HD + dd;
                    __nv_bfloat162 hv; hv.x = h0; hv.y = h1;
                    __nv_bfloat162 lv; lv.x = __float2bfloat16(l0); lv.y = __float2bfloat16(l1);
                    *(__nv_bfloat162*)&hp[idx] = hv;
                    *(__nv_bfloat162*)&lp[idx] = lv;
                }
            } else if (mode == 3) {
                #pragma unroll
                for (int ni = 0; ni < 4; ni++) {
                    int n = n_base + ni * 8 + lc;
                    float v0 = c[mi][ni][rr * 2 + 0] * sc;
                    float v1 = c[mi][ni][rr * 2 + 1] * sc;
                    float2 o;
                    o.x = v0 / (1.0f + expf(-v0));
                    o.y = v1 / (1.0f + expf(-v1));
                    *(float2*)&g_G[(size_t)m * DIM + n] = o;
                }
            } else {
                #pragma unroll
                for (int ni = 0; ni < 4; ni++) {
                    int n = n_base + ni * 8 + lc;
                    float2 o;
                    o.x = c[mi][ni][rr * 2 + 0] * sc;
                    o.y = c[mi][ni][rr * 2 + 1] * sc;
                    *(float2*)&dst[(size_t)m * DIM + n] = o;
                }
            }
        }
    }
}

// ---------------- attention: register-resident S + smem decay window ----------------
#define BP 72
#define ATT_TILE (64 * BP)
#define ATT_SMEM (6 * ATT_TILE * 2 + 512)

__global__ void __launch_bounds__(256) k_attn_mma() {
    extern __shared__ __nv_bfloat16 dyn[];
    __nv_bfloat16 *sQh = dyn,                *sQl = dyn + ATT_TILE;
    __nv_bfloat16 *sKh = dyn + 2 * ATT_TILE, *sKl = dyn + 3 * ATT_TILE;
    __nv_bfloat16 *sVh = dyn + 4 * ATT_TILE, *sVl = dyn + 5 * ATT_TILE;
    float* sdec = (float*)(dyn + 6 * ATT_TILE);
    float* red = (float*)(dyn + 2 * ATT_TILE);   // overlays K after main loop

    int nt = (NSEQ / 64 - 1) - blockIdx.x;
    int h = blockIdx.y, b = blockIdx.z;
    int n0 = nt * 64;
    size_t base = ((size_t)(b * NH + h)) * NSEQ * HD;
    const __nv_bfloat16 *Qhp = g_Qh + base, *Qlp = g_Ql + base;
    const __nv_bfloat16 *Khp = g_Kh + base, *Klp = g_Kl + base;
    const __nv_bfloat16 *Vhp = g_Vh + base, *Vlp = g_Vl + base;

    // per-head decay constants (double, matches old table to ~1e-7)
    double lina = log(1.0 / 32.0), linb = log(1.0 / 512.0);
    double lin = lina + (linb - lina) * ((double)h / 15.0);
    double gamma = 1.0 - exp(lin);
    double lg = log(gamma);
    float l2gf = (float)(lg * 1.4426950408889634);
    int dcut = (int)(13.815510557964274 / (-lg)) + 1;

    int tid = threadIdx.x;
    int warp = tid >> 5, lane = tid & 31;
    int wm = warp & 3, wn = warp >> 2;

    uint32_t aQh = (uint32_t)__cvta_generic_to_shared(sQh);
    uint32_t aQl = (uint32_t)__cvta_generic_to_shared(sQl);
    uint32_t aKh = (uint32_t)__cvta_generic_to_shared(sKh);
    uint32_t aKl = (uint32_t)__cvta_generic_to_shared(sKl);
    uint32_t aVh = (uint32_t)__cvta_generic_to_shared(sVh);
    uint32_t aVl = (uint32_t)__cvta_generic_to_shared(sVl);

    for (int j = tid; j < 512; j += 256) {
        int r = j >> 3, c8 = (j & 7) * 8;
        *(uint4*)&sQh[r * BP + c8] = *(const uint4*)(Qhp + (size_t)(n0 + r) * HD + c8);
        *(uint4*)&sQl[r * BP + c8] = *(const uint4*)(Qlp + (size_t)(n0 + r) * HD + c8);
    }

    int a_row = wm * 16 + (lane & 15);
    int a_sel = (lane >> 4) << 3;
    int bq_row = wn * 32 + (lane & 7) + (((lane >> 4) & 1) << 3);
    int bq_col = ((lane >> 3) & 1) << 3;
    int bv_row = lane & 15;
    int bv_sel = ((lane >> 4) & 1) << 3;
    int lr = lane >> 2, lc2 = (lane & 3) * 2;

    float yacc[8][4];
    #pragma unroll
    for (int i = 0; i < 8; i++)
        #pragma unroll
        for (int r = 0; r < 4; r++) yacc[i][r] = 0.0f;

    int lim = n0 - 63 - dcut;
    int mt0 = (lim > 0) ? ((lim + 63) >> 6) : 0;

    for (int mt = mt0; mt <= nt; ++mt) {
        int m0 = mt * 64;
        __syncthreads();
        for (int j = tid; j < 512; j += 256) {
            int r = j >> 3, c8 = (j & 7) * 8;
            *(uint4*)&sKh[r * BP + c8] = *(const uint4*)(Khp + (size_t)(m0 + r) * HD + c8);
            *(uint4*)&sKl[r * BP + c8] = *(const uint4*)(Klp + (size_t)(m0 + r) * HD + c8);
            *(uint4*)&sVh[r * BP + c8] = *(const uint4*)(Vhp + (size_t)(m0 + r) * HD + c8);
            *(uint4*)&sVl[r * BP + c8] = *(const uint4*)(Vlp + (size_t)(m0 + r) * HD + c8);
        }
        if (tid < 128) {
            int d = (n0 - m0) - 64 + tid;
            sdec[tid] = (d >= 0) ? exp2f((float)d * l2gf) : 0.0f;
        }
        __syncthreads();

        // ---- S = Q K^T (3-term hi/lo) ----
        float sacc[4][4];
        #pragma unroll
        for (int ni = 0; ni < 4; ni++)
            #pragma unroll
            for (int r = 0; r < 4; r++) sacc[ni][r] = 0.0f;

        #pragma unroll
        for (int ks = 0; ks < 4; ks++) {
            uint32_t ah[4], al[4], bh[2][4], bl[2][4];
            uint32_t aoff = (uint32_t)(a_row * BP + ks * 16 + a_sel) * 2u;
            ldmx4(ah[0], ah[1], ah[2], ah[3], aQh + aoff);
            ldmx4(al[0], al[1], al[2], al[3], aQl + aoff);
            #pragma unroll
            for (int p = 0; p < 2; p++) {
                uint32_t boff = (uint32_t)((bq_row + p * 16) * BP + ks * 16 + bq_col) * 2u;
                ldmx4(bh[p][0], bh[p][1], bh[p][2], bh[p][3], aKh + boff);
                ldmx4(bl[p][0], bl[p][1], bl[p][2], bl[p][3], aKl + boff);
            }
            #pragma unroll
            for (int ni = 0; ni < 4; ni++) {
                int p = ni >> 1, q2 = (ni & 1) * 2;
                mma16816(sacc[ni], ah, bh[p][q2], bh[p][q2 + 1]);
                mma16816(sacc[ni], ah, bl[p][q2], bl[p][q2 + 1]);
                mma16816(sacc[ni], al, bh[p][q2], bh[p][q2 + 1]);
            }
        }

        // ---- decay (smem window, branch-free) + hi/lo split, C-frag -> A-frag ----
        uint32_t shf[2][4], slf[2][4];
        #pragma unroll
        for (int ni = 0; ni < 4; ni++) {
            int col0 = wn * 32 + ni * 8 + lc2;
            #pragma unroll
            for (int half = 0; half < 2; half++) {
                int row = wm * 16 + lr + half * 8;
                int widx = row - col0 + 64;
                float v0 = sacc[ni][half * 2 + 0] * sdec[widx];
                float v1 = sacc[ni][half * 2 + 1] * sdec[widx - 1];
                uint32_t hr = packbf2(v0, v1);
                __nv_bfloat162 hb = *reinterpret_cast<__nv_bfloat162*>(&hr);
                float l0 = v0 - __bfloat162float(hb.x);
                float l1 = v1 - __bfloat162float(hb.y);
                shf[ni >> 1][(ni & 1) * 2 + half] = hr;
                slf[ni >> 1][(ni & 1) * 2 + half] = packbf2(l0, l1);
            }
        }

        // ---- Y_partial += S V ----
        #pragma unroll
        for (int ks2 = 0; ks2 < 2; ks2++) {
            #pragma unroll
            for (int t = 0; t < 4; t++) {
                uint32_t bh[4], bl[4];
                uint32_t voff = (uint32_t)((wn * 32 + ks2 * 16 + bv_row) * BP
                                           + t * 16 + bv_sel) * 2u;
                ldmx4t(bh[0], bh[1], bh[2], bh[3], aVh + voff);
                ldmx4t(bl[0], bl[1], bl[2], bl[3], aVl + voff);
                #pragma unroll
                for (int j = 0; j < 2; j++) {
                    mma16816(yacc[t * 2 + j], shf[ks2], bh[j * 2], bh[j * 2 + 1]);
                    mma16816(yacc[t * 2 + j], shf[ks2], bl[j * 2], bl[j * 2 + 1]);
                    mma16816(yacc[t * 2 + j], slf[ks2], bh[j * 2], bh[j * 2 + 1]);
                }
            }
        }
    }

    // ---- merge wn halves via smem ----
    __syncthreads();
    if (wn == 1) {
        #pragma unroll
        for (int d8 = 0; d8 < 8; d8++)
            #pragma unroll
            for (int r = 0; r < 4; r++) {
                int row = wm * 16 + lr + (r >> 1) * 8;
                int dd = d8 * 8 + lc2 + (r & 1);
                red[row * 64 + dd] = yacc[d8][r];
            }
    }
    __syncthreads();
    if (wn == 0) {
        #pragma unroll
        for (int d8 = 0; d8 < 8; d8++)
            #pragma unroll
            for (int half = 0; half < 2; half++) {
                int row = wm * 16 + lr + half * 8;
                int dd = d8 * 8 + lc2;
                float2 o;
                o.x = yacc[d8][half * 2 + 0] + red[row * 64 + dd];
                o.y = yacc[d8][half * 2 + 1] + red[row * 64 + dd + 1];
                *(float2*)&g_Y[(size_t)(b * NSEQ + n0 + row) * DIM + h * HD + dd] = o;
            }
    }
}

// ---------------- LN(y)*silu(g) + per-row double partials ----------------
__global__ void k_lng(const float* __restrict__ lnw, const float* __restrict__ lnb) {
    int row = blockIdx.x;
    const float* y = g_Y + (size_t)row * DIM;
    int c0 = threadIdx.x * 4;
    float4 yv = *(const float4*)(y + c0);

    __shared__ double shs[256], shq[256];
    shs[threadIdx.x] = (double)yv.x + yv.y + yv.z + yv.w;
    shq[threadIdx.x] = (double)yv.x*yv.x + (double)yv.y*yv.y
                     + (double)yv.z*yv.z + (double)yv.w*yv.w;
    __syncthreads();
    for (int o = 128; o > 0; o >>= 1) {
        if (threadIdx.x < o) {
            shs[threadIdx.x] += shs[threadIdx.x + o];
            shq[threadIdx.x] += shq[threadIdx.x + o];
        }
        __syncthreads();
    }
    double mu_d  = shs[0] / (double)DIM;
    double var_d = shq[0] / (double)DIM - mu_d * mu_d;
    float mu = (float)mu_d;
    float rs = (float)(1.0 / sqrt(var_d + 1e-5));
    __syncthreads();

    float4 g4 = *(const float4*)(g_G + (size_t)row * DIM + c0);
    float4 w4 = *(const float4*)(lnw + c0);
    float4 b4 = *(const float4*)(lnb + c0);
    float4 z;
    z.x = ((yv.x - mu) * rs * w4.x + b4.x) * g4.x;
    z.y = ((yv.y - mu) * rs * w4.y + b4.y) * g4.y;
    z.z = ((yv.z - mu) * rs * w4.z + b4.z) * g4.z;
    z.w = ((yv.w - mu) * rs * w4.w + b4.w) * g4.w;
    *(float4*)&g_Z[(size_t)row * DIM + c0] = z;

    shs[threadIdx.x] = (double)z.x + z.y + z.z + z.w;
    shq[threadIdx.x] = (double)z.x*z.x + (double)z.y*z.y
                     + (double)z.z*z.z + (double)z.w*z.w;
    __syncthreads();
    for (int o = 128; o > 0; o >>= 1) {
        if (threadIdx.x < o) {
            shs[threadIdx.x] += shs[threadIdx.x + o];
            shq[threadIdx.x] += shq[threadIdx.x + o];
        }
        __syncthreads();
    }
    if (threadIdx.x == 0) {
        g_zpart_s[row] = shs[0];
        g_zpart_q[row] = shq[0];
    }
}

__global__ void k_fin2() {
    int b = blockIdx.x;
    double s = 0.0, q = 0.0;
    for (int i = threadIdx.x; i < NSEQ; i += 256) {
        s += g_zpart_s[b * NSEQ + i];
        q += g_zpart_q[b * NSEQ + i];
    }
    __shared__ double shs[256], shq[256];
    shs[threadIdx.x] = s; shq[threadIdx.x] = q; __syncthreads();
    for (int o = 128; o > 0; o >>= 1) {
        if (threadIdx.x < o) {
            shs[threadIdx.x] += shs[threadIdx.x + o];
            shq[threadIdx.x] += shq[threadIdx.x + o];
        }
        __syncthreads();
    }
    if (threadIdx.x == 0) {
        double n = (double)BELEMS;
        double mu = shs[0] / n;
        double var = shq[0] / n - mu * mu;
        g_zmu[b]   = (float)mu;
        g_zrstd[b] = (float)(1.0 / sqrt(var + 1e-5));
    }
}

// ---------------- launch ----------------
extern "C" void kernel_launch(void* const* d_in, const int* in_sizes, int n_in,
                              void* d_out, int out_size) {
    (void)in_sizes; (void)n_in; (void)out_size;
    const float* x   = (const float*)d_in[0];
    const float* wq  = (const float*)d_in[1];
    const float* wk  = (const float*)d_in[2];
    const float* wv  = (const float*)d_in[3];
    const float* wg  = (const float*)d_in[4];
    const float* wo  = (const float*)d_in[5];
    const float* lnw = (const float*)d_in[6];
    const float* lnb = (const float*)d_in[7];
    float* out = (float*)d_out;

    cudaFuncSetAttribute(k_attn_mma,
                         cudaFuncAttributeMaxDynamicSharedMemorySize, ATT_SMEM);

    k_reduce_all <<<dim3(64, 7),     256>>>(x, wq, wk, wv, wg, wo);   // 1
    k_fin1       <<<1, 32>>>();                                       // 2
    k_prep       <<<dim3(4096, 6),   256>>>(x, wq, wk, wv, wg, wo);   // 3
    k_gemm_mma   <<<dim3(8, 32, 4),  256>>>(0, out);                  // 4
    k_attn_mma   <<<dim3(NSEQ/64, NH, BATCH), 256, ATT_SMEM>>>();     // 5
    k_lng        <<<ROWS, 256>>>(lnw, lnb);                           // 6
    k_fin2       <<<BATCH, 256>>>();                                  // 7
    k_qact2      <<<ROWS, 256>>>();                                   // 8
    k_gemm_mma   <<<dim3(8, 32, 1),  256>>>(4, out);                  // 9
}